// round 7
// baseline (speedup 1.0000x reference)
#include <cuda_runtime.h>
#include <math.h>

#define N_NODES 5000
#define DEG 16
#define S 17
#define T 10
#define MN 10
#define D 128
#define EPS 0.1f
#define N_OUTER 3
#define N_SINK 5
#define TM 100
#define NPB 10
#define LOG2E 1.4426950408889634f
#define LN2 0.6931471805599453f
#define FULLMASK 0xffffffffu

__device__ __forceinline__ float ex2(float x) {
    float r; asm("ex2.approx.ftz.f32 %0, %1;" : "=f"(r) : "f"(x)); return r;
}

// ---------------- device-global precomputed state / scratch ----------------
__device__ float g_alpha;
__device__ float g_C2[T*MN*MN];
__device__ float g_q[T*MN];
__device__ float g_hC2[T*MN];
__device__ float g_Hq[T*MN];
__device__ float g_f2sq[T*MN];
__device__ float g_Pm[(size_t)N_NODES * TM];   // -2<x_n,F2_tm>
__device__ float g_xsq[N_NODES];

// ---------------- kernel 1: fused Pm GEMM + tiny precompute (block 0) ------
__global__ __launch_bounds__(512) void pm_pre_kernel(const float* __restrict__ x,
                                                     const float* __restrict__ tf,
                                                     const float* __restrict__ tmpl,
                                                     const float* __restrict__ q0,
                                                     const float* __restrict__ alpha0) {
    __shared__ __align__(16) float4 sx4[NPB][D/4];
    int base = blockIdx.x * NPB;
    int tid = threadIdx.x;

    for (int idx = tid; idx < NPB*(D/4); idx += 512) {
        int r = idx / (D/4), c = idx % (D/4);
        sx4[r][c] = ((const float4*)(x + (size_t)(base + r)*D))[c];
    }
    __syncthreads();
    if (tid < NPB) {
        float s = 0.f;
        #pragma unroll 8
        for (int d = 0; d < D/4; d++) {
            float4 v = sx4[tid][d];
            s += v.x*v.x + v.y*v.y + v.z*v.z + v.w*v.w;
        }
        g_xsq[base + tid] = s;
    }
    if (tid < NPB * (TM/2)) {
        int nl = tid % NPB, tm0 = (tid / NPB) * 2;
        const float4* b0 = (const float4*)(tf + (size_t)(tm0+0)*D);
        const float4* b1 = (const float4*)(tf + (size_t)(tm0+1)*D);
        float a0 = 0.f, a1 = 0.f;
        #pragma unroll 8
        for (int d = 0; d < D/4; d++) {
            float4 av = sx4[nl][d];
            float4 r0 = b0[d], r1 = b1[d];
            a0 += av.x*r0.x + av.y*r0.y + av.z*r0.z + av.w*r0.w;
            a1 += av.x*r1.x + av.y*r1.y + av.z*r1.z + av.w*r1.w;
        }
        size_t o = (size_t)(base + nl)*TM + tm0;
        g_Pm[o+0] = -2.f*a0;
        g_Pm[o+1] = -2.f*a1;
    }

    if (blockIdx.x == 0) {
        if (tid == 0) g_alpha = 1.0f / (1.0f + expf(-alpha0[0]));
        if (tid < T) {
            float mx = -1e30f;
            for (int m = 0; m < MN; m++) mx = fmaxf(mx, q0[tid*MN + m]);
            float s = 0.f, e[MN];
            for (int m = 0; m < MN; m++) { e[m] = expf(q0[tid*MN + m] - mx); s += e[m]; }
            for (int m = 0; m < MN; m++) g_q[tid*MN + m] = e[m] / s;
        }
        if (tid < T*MN) {
            int t = tid / MN, j = tid % MN;
            float mx = -1e30f;
            for (int i = 0; i < MN; i++) mx = fmaxf(mx, tmpl[(t*MN + i)*MN + j]);
            float s = 0.f, e[MN];
            for (int i = 0; i < MN; i++) { e[i] = expf(tmpl[(t*MN + i)*MN + j] - mx); s += e[i]; }
            for (int i = 0; i < MN; i++) g_C2[(t*MN + i)*MN + j] = e[i] / s;
        }
        if (tid < T*MN) {
            float s = 0.f;
            const float4* row = (const float4*)(tf + (size_t)tid * D);
            #pragma unroll 8
            for (int d = 0; d < D/4; d++) {
                float4 v = row[d];
                s += v.x*v.x + v.y*v.y + v.z*v.z + v.w*v.w;
            }
            g_f2sq[tid] = s;
        }
        __syncthreads();
        if (tid < T*MN) {
            int t = tid / MN, l = tid % MN;
            float s = 0.f, hq = 0.f;
            for (int k = 0; k < MN; k++) {
                float c = g_C2[(t*MN + l)*MN + k];
                float qq = g_q[t*MN + k];
                s += c * c * qq;
                hq += c * qq;
            }
            g_hC2[tid] = s;
            g_Hq[tid]  = hq;
        }
    }
}

// ---------------- kernel 2: FGW — KT in regs, scalars via broadcast smem ---
__global__ __launch_bounds__(320, 3) void ltfgw_kernel(const int* __restrict__ dst,
                                                       float* __restrict__ out) {
    __shared__ __align__(16) float sC2[T][MN][12];   // zero-padded rows
    __shared__ float kbuf[T][S][11];                 // stride-11: conflict-free
    __shared__ __align__(16) float vbuf[T][12];
    __shared__ __align__(16) float wbuf[T][20];
    __shared__ __align__(16) float h0buf[T][12];
    __shared__ __align__(16) float sHq[T][12];
    __shared__ __align__(16) float shC2[T][12];
    __shared__ float sF2[T][MN];
    __shared__ unsigned smask[S];
    __shared__ int ids[S];

    int n = blockIdx.x, tid = threadIdx.x;

    if (tid < S) {
        ids[tid] = (tid == 0) ? n : dst[n*DEG + tid - 1];
        smask[tid] = 0u;
    }
    for (int idx = tid; idx < T*MN*12; idx += 320) {
        int t0 = idx / (MN*12), rem = idx % (MN*12);
        int l0 = rem / 12, k0 = rem % 12;
        ((float*)sC2)[idx] = (k0 < MN) ? g_C2[(t0*MN + l0)*MN + k0] : 0.f;
    }
    for (int idx = tid; idx < T*MN; idx += 320) {
        int t0 = idx / MN, l0 = idx % MN;
        sHq[t0][l0]  = g_Hq[idx];
        shC2[t0][l0] = g_hC2[idx];
        sF2[t0][l0]  = g_f2sq[idx];
    }
    __syncthreads();

    for (int e = tid; e < S*DEG; e += 320) {
        int a = e / DEG, k = e % DEG;
        int nb = dst[ids[a]*DEG + k];
        #pragma unroll
        for (int b = 0; b < S; b++) {
            if (ids[b] == nb) { atomicOr(&smask[a], 1u << b); atomicOr(&smask[b], 1u << a); }
        }
    }
    __syncthreads();
    if (tid < S) smask[tid] &= ~(1u << tid);
    __syncthreads();

    const float alpha = g_alpha;
    const float oma = 1.0f - alpha;
    const float cE = (1.0f/EPS) * LOG2E;
    const float invcE = EPS * LN2;
    const float c3 = 4.0f * alpha * (1.0f/EPS) * LOG2E;
    const float m2a = -2.0f * alpha;

    int t = tid >> 5, lane = tid & 31;
    bool rowact = lane < S;
    bool colact = lane < MN;
    int i = rowact ? lane : 0;
    unsigned mask_i = rowact ? smask[i] : 0u;
    float hc1 = __popc(mask_i) * (1.0f / S);
    unsigned extra = (lane == 0 || !rowact) ? 0u : (mask_i & ~1u);

    // outer-invariant exponent bases
    float Earg[MN], Fbase;
    {
        int id = ids[i];
        float xs = g_xsq[id];
        const float2* pm2 = (const float2*)(g_Pm + (size_t)id*TM + t*MN);
        float pmv[MN];
        #pragma unroll
        for (int h = 0; h < 5; h++) { float2 p = __ldg(&pm2[h]); pmv[2*h] = p.x; pmv[2*h+1] = p.y; }
        float M0 = xs + sF2[t][0] + pmv[0];
        Fbase = oma * M0;
        #pragma unroll
        for (int l = 0; l < MN; l++) {
            float Ml = xs + sF2[t][l] + pmv[l];
            float hh = hc1 + shC2[t][l];
            Earg[l] = rowact ? (oma*(M0 - Ml) - 2.f*alpha*hh) * cE : -1000.f;
        }
    }
    float qcol = __ldg(&g_q[t*MN + (colact ? lane : 0)]);

    // K init = q/S (w pre-folded); v = 1
    float K[MN];
    #pragma unroll
    for (int l = 0; l < MN; l++) K[l] = rowact ? __ldg(&g_q[t*MN + l]) * (1.0f/S) : 0.f;
    if (colact) vbuf[t][lane] = 1.0f;
    __syncwarp();

    for (int it = 0; it <= N_OUTER; it++) {
        // v broadcast from smem (all lanes, identical addresses)
        float vv[MN];
        {
            float4 a0 = *(const float4*)&vbuf[t][0];
            float4 a1 = *(const float4*)&vbuf[t][4];
            float2 a2 = *(const float2*)&vbuf[t][8];
            vv[0]=a0.x; vv[1]=a0.y; vv[2]=a0.z; vv[3]=a0.w;
            vv[4]=a1.x; vv[5]=a1.y; vv[6]=a1.z; vv[7]=a1.w;
            vv[8]=a2.x; vv[9]=a2.y;
        }
        // H0 only (column-marginal identity): lane l computes H0[l]
        float g0[MN];
        #pragma unroll
        for (int k = 0; k < MN; k++) g0[k] = __shfl_sync(FULLMASK, K[k], 0) * vv[k];
        if (colact) {
            float4 c0 = *(const float4*)&sC2[t][lane][0];
            float4 c1 = *(const float4*)&sC2[t][lane][4];
            float2 c2 = *(const float2*)&sC2[t][lane][8];
            h0buf[t][lane] = g0[0]*c0.x + g0[1]*c0.y + g0[2]*c0.z + g0[3]*c0.w
                           + g0[4]*c1.x + g0[5]*c1.y + g0[6]*c1.z + g0[7]*c1.w
                           + g0[8]*c2.x + g0[9]*c2.y;
        }
        __syncwarp();
        float A[MN];
        {
            float4 a0 = *(const float4*)&h0buf[t][0];
            float4 a1 = *(const float4*)&h0buf[t][4];
            float2 a2 = *(const float2*)&h0buf[t][8];
            A[0]=a0.x; A[1]=a0.y; A[2]=a0.z; A[3]=a0.w;
            A[4]=a1.x; A[5]=a1.y; A[6]=a1.z; A[7]=a1.w;
            A[8]=a2.x; A[9]=a2.y;
        }
        if (lane == 0) {
            float4 q0v = *(const float4*)&sHq[t][0];
            float4 q1v = *(const float4*)&sHq[t][4];
            float2 q2v = *(const float2*)&sHq[t][8];
            A[0]=q0v.x-A[0]; A[1]=q0v.y-A[1]; A[2]=q0v.z-A[2]; A[3]=q0v.w-A[3];
            A[4]=q1v.x-A[4]; A[5]=q1v.y-A[5]; A[6]=q1v.z-A[6]; A[7]=q1v.w-A[7];
            A[8]=q2v.x-A[8]; A[9]=q2v.y-A[9];
        }
        // rare extra edges among neighbors
        unsigned ex = extra;
        while (__any_sync(FULLMASK, ex)) {
            bool has = (ex != 0u);
            int j = has ? (__ffs(ex) - 1) : 0;
            ex &= ex - 1u;
            float gj[MN];
            #pragma unroll
            for (int k = 0; k < MN; k++) gj[k] = __shfl_sync(FULLMASK, K[k], j) * vv[k];
            #pragma unroll
            for (int l = 0; l < MN; l++) {
                float4 c0 = *(const float4*)&sC2[t][l][0];
                float4 c1 = *(const float4*)&sC2[t][l][4];
                float2 c2 = *(const float2*)&sC2[t][l][8];
                float hj = gj[0]*c0.x + gj[1]*c0.y + gj[2]*c0.z + gj[3]*c0.w
                         + gj[4]*c1.x + gj[5]*c1.y + gj[6]*c1.z + gj[7]*c1.w
                         + gj[8]*c2.x + gj[9]*c2.y;
                if (has) A[l] += hj;
            }
        }

        if (it == N_OUTER) {
            float acc = 0.f;
            #pragma unroll
            for (int l = 0; l < MN; l++) {
                float hh = hc1 + shC2[t][l];
                float Fl = Fbase - Earg[l]*invcE - alpha*hh;
                acc += K[l]*vv[l] * fmaf(m2a, A[l], Fl);
            }
            acc += __shfl_xor_sync(FULLMASK, acc, 16);
            acc += __shfl_xor_sync(FULLMASK, acc, 8);
            acc += __shfl_xor_sync(FULLMASK, acc, 4);
            acc += __shfl_xor_sync(FULLMASK, acc, 2);
            acc += __shfl_xor_sync(FULLMASK, acc, 1);
            if (lane == 0) out[n*T + t] = acc;
            return;
        }

        // K = exp2(Earg + c3*A)
        #pragma unroll
        for (int l = 0; l < MN; l++) K[l] = ex2(fmaf(c3, A[l], Earg[l]));

        // transpose K -> kbuf (conflict-free), reset v
        if (rowact) {
            #pragma unroll
            for (int l = 0; l < MN; l++) kbuf[t][lane][l] = K[l];
        }
        if (colact) vbuf[t][lane] = 1.0f;
        __syncwarp();
        float KT[S];
        if (colact) {
            #pragma unroll
            for (int ii = 0; ii < S; ii++) KT[ii] = kbuf[t][ii][lane];
        }

        // Sinkhorn: scalars move through broadcast smem, matrices in regs
        float w = 0.f;
        #pragma unroll
        for (int si = 0; si < N_SINK; si++) {
            float4 b0 = *(const float4*)&vbuf[t][0];
            float4 b1 = *(const float4*)&vbuf[t][4];
            float2 b2 = *(const float2*)&vbuf[t][8];
            float rs = K[0]*b0.x + K[1]*b0.y + K[2]*b0.z + K[3]*b0.w
                     + K[4]*b1.x + K[5]*b1.y + K[6]*b1.z + K[7]*b1.w
                     + K[8]*b2.x + K[9]*b2.y;
            w = rowact ? __fdividef(1.0f / S, rs) : 0.f;
            if (rowact) wbuf[t][lane] = w;
            __syncwarp();
            if (colact) {
                float4 w0 = *(const float4*)&wbuf[t][0];
                float4 w1 = *(const float4*)&wbuf[t][4];
                float4 w2 = *(const float4*)&wbuf[t][8];
                float4 w3 = *(const float4*)&wbuf[t][12];
                float  w4 = wbuf[t][16];
                float cs = KT[0]*w0.x + KT[1]*w0.y + KT[2]*w0.z + KT[3]*w0.w
                         + KT[4]*w1.x + KT[5]*w1.y + KT[6]*w1.z + KT[7]*w1.w
                         + KT[8]*w2.x + KT[9]*w2.y + KT[10]*w2.z + KT[11]*w2.w
                         + KT[12]*w3.x + KT[13]*w3.y + KT[14]*w3.z + KT[15]*w3.w
                         + KT[16]*w4;
                vbuf[t][lane] = __fdividef(qcol, cs);
            }
            __syncwarp();
        }
        // fold w into K (G = diag(w) K diag(v))
        #pragma unroll
        for (int l = 0; l < MN; l++) K[l] *= w;
    }
}

// ---------------- launch ----------------------------------------------------
extern "C" void kernel_launch(void* const* d_in, const int* in_sizes, int n_in,
                              void* d_out, int out_size) {
    const float* x      = (const float*)d_in[0];
    const int*   edge   = (const int*)  d_in[1];
    const float* tmpl   = (const float*)d_in[2];
    const float* tf     = (const float*)d_in[3];
    const float* q0     = (const float*)d_in[4];
    const float* alpha0 = (const float*)d_in[5];
    const int*   dst    = edge + N_NODES*DEG;
    float* out = (float*)d_out;

    pm_pre_kernel<<<N_NODES/NPB, 512>>>(x, tf, tmpl, q0, alpha0);
    ltfgw_kernel<<<N_NODES, 320>>>(dst, out);
}

// round 8
// speedup vs baseline: 1.8624x; 1.8624x over previous
#include <cuda_runtime.h>
#include <math.h>

#define N_NODES 5000
#define DEG 16
#define S 17
#define T 10
#define MN 10
#define D 128
#define EPS 0.1f
#define N_OUTER 3
#define N_SINK 5
#define TM 100
#define NPB 10
#define LOG2E 1.4426950408889634f
#define LN2 0.6931471805599453f
#define FULLMASK 0xffffffffu

__device__ __forceinline__ float ex2(float x) {
    float r; asm("ex2.approx.ftz.f32 %0, %1;" : "=f"(r) : "f"(x)); return r;
}

// ---------------- device-global precomputed state / scratch ----------------
__device__ float g_alpha;
__device__ float g_C2[T*MN*MN];
__device__ float g_q[T*MN];
__device__ float g_hC2[T*MN];
__device__ float g_Hq[T*MN];
__device__ float g_f2sq[T*MN];
__device__ float g_Pm[(size_t)N_NODES * TM];   // -2<x_n,F2_tm>
__device__ float g_xsq[N_NODES];

// ---------------- kernel 1: Pm GEMM (R5 body) + fused precompute ----------
__global__ __launch_bounds__(256) void pm_pre_kernel(const float* __restrict__ x,
                                                     const float* __restrict__ tf,
                                                     const float* __restrict__ tmpl,
                                                     const float* __restrict__ q0,
                                                     const float* __restrict__ alpha0) {
    __shared__ __align__(16) float4 sx4[NPB][D/4];
    int base = blockIdx.x * NPB;
    int tid = threadIdx.x;

    for (int idx = tid; idx < NPB*(D/4); idx += 256) {
        int r = idx / (D/4), c = idx % (D/4);
        sx4[r][c] = ((const float4*)(x + (size_t)(base + r)*D))[c];
    }
    __syncthreads();
    if (tid < NPB) {
        float s = 0.f;
        #pragma unroll 8
        for (int d = 0; d < D/4; d++) {
            float4 v = sx4[tid][d];
            s += v.x*v.x + v.y*v.y + v.z*v.z + v.w*v.w;
        }
        g_xsq[base + tid] = s;
    }
    if (tid < NPB * (TM/4)) {
        int nl = tid % NPB, tm0 = (tid / NPB) * 4;
        const float4* b0 = (const float4*)(tf + (size_t)(tm0+0)*D);
        const float4* b1 = (const float4*)(tf + (size_t)(tm0+1)*D);
        const float4* b2 = (const float4*)(tf + (size_t)(tm0+2)*D);
        const float4* b3 = (const float4*)(tf + (size_t)(tm0+3)*D);
        float a0=0.f, a1=0.f, a2=0.f, a3=0.f;
        #pragma unroll 8
        for (int d = 0; d < D/4; d++) {
            float4 av = sx4[nl][d];
            float4 r0 = b0[d], r1 = b1[d], r2 = b2[d], r3 = b3[d];
            a0 += av.x*r0.x + av.y*r0.y + av.z*r0.z + av.w*r0.w;
            a1 += av.x*r1.x + av.y*r1.y + av.z*r1.z + av.w*r1.w;
            a2 += av.x*r2.x + av.y*r2.y + av.z*r2.z + av.w*r2.w;
            a3 += av.x*r3.x + av.y*r3.y + av.z*r3.z + av.w*r3.w;
        }
        size_t o = (size_t)(base + nl)*TM + tm0;
        g_Pm[o+0] = -2.f*a0; g_Pm[o+1] = -2.f*a1;
        g_Pm[o+2] = -2.f*a2; g_Pm[o+3] = -2.f*a3;
    }

    if (blockIdx.x == 0) {
        if (tid == 0) g_alpha = 1.0f / (1.0f + expf(-alpha0[0]));
        if (tid < T) {
            float mx = -1e30f;
            for (int m = 0; m < MN; m++) mx = fmaxf(mx, q0[tid*MN + m]);
            float s = 0.f, e[MN];
            for (int m = 0; m < MN; m++) { e[m] = expf(q0[tid*MN + m] - mx); s += e[m]; }
            for (int m = 0; m < MN; m++) g_q[tid*MN + m] = e[m] / s;
        }
        if (tid < T*MN) {
            int t = tid / MN, j = tid % MN;
            float mx = -1e30f;
            for (int i = 0; i < MN; i++) mx = fmaxf(mx, tmpl[(t*MN + i)*MN + j]);
            float s = 0.f, e[MN];
            for (int i = 0; i < MN; i++) { e[i] = expf(tmpl[(t*MN + i)*MN + j] - mx); s += e[i]; }
            for (int i = 0; i < MN; i++) g_C2[(t*MN + i)*MN + j] = e[i] / s;
        }
        if (tid < T*MN) {
            float s = 0.f;
            const float4* row = (const float4*)(tf + (size_t)tid * D);
            #pragma unroll 8
            for (int d = 0; d < D/4; d++) {
                float4 v = row[d];
                s += v.x*v.x + v.y*v.y + v.z*v.z + v.w*v.w;
            }
            g_f2sq[tid] = s;
        }
        __syncthreads();
        if (tid < T*MN) {
            int t = tid / MN, l = tid % MN;
            float s = 0.f, hq = 0.f;
            for (int k = 0; k < MN; k++) {
                float c = g_C2[(t*MN + l)*MN + k];
                float qq = g_q[t*MN + k];
                s += c * c * qq;
                hq += c * qq;
            }
            g_hC2[tid] = s;
            g_Hq[tid]  = hq;
        }
    }
}

// ---------------- kernel 2: FGW — shfl Sinkhorn, H0-only, no reg cap -------
__global__ __launch_bounds__(320, 2) void ltfgw_kernel(const int* __restrict__ dst,
                                                       float* __restrict__ out) {
    __shared__ __align__(16) float sC2[T][MN][12];   // zero-padded rows
    __shared__ float kbuf[T][S][11];                 // conflict-free transpose
    __shared__ __align__(16) float h0buf[T][12];
    __shared__ __align__(16) float sHq[T][12];
    __shared__ __align__(16) float shC2[T][12];
    __shared__ float sF2[T][MN];
    __shared__ unsigned smask[S];
    __shared__ int ids[S];

    int n = blockIdx.x, tid = threadIdx.x;

    if (tid < S) {
        ids[tid] = (tid == 0) ? n : dst[n*DEG + tid - 1];
        smask[tid] = 0u;
    }
    for (int idx = tid; idx < T*MN*12; idx += 320) {
        int t0 = idx / (MN*12), rem = idx % (MN*12);
        int l0 = rem / 12, k0 = rem % 12;
        ((float*)sC2)[idx] = (k0 < MN) ? g_C2[(t0*MN + l0)*MN + k0] : 0.f;
    }
    for (int idx = tid; idx < T*MN; idx += 320) {
        int t0 = idx / MN, l0 = idx % MN;
        sHq[t0][l0]  = g_Hq[idx];
        shC2[t0][l0] = g_hC2[idx];
        sF2[t0][l0]  = g_f2sq[idx];
    }
    __syncthreads();

    for (int e = tid; e < S*DEG; e += 320) {
        int a = e / DEG, k = e % DEG;
        int nb = dst[ids[a]*DEG + k];
        #pragma unroll
        for (int b = 0; b < S; b++) {
            if (ids[b] == nb) { atomicOr(&smask[a], 1u << b); atomicOr(&smask[b], 1u << a); }
        }
    }
    __syncthreads();
    if (tid < S) smask[tid] &= ~(1u << tid);
    __syncthreads();

    const float alpha = g_alpha;
    const float oma = 1.0f - alpha;
    const float cE = (1.0f/EPS) * LOG2E;
    const float invcE = EPS * LN2;
    const float c3 = 4.0f * alpha * (1.0f/EPS) * LOG2E;
    const float m2a = -2.0f * alpha;

    int t = tid >> 5, lane = tid & 31;
    bool rowact = lane < S;
    bool colact = lane < MN;
    int i = rowact ? lane : 0;
    unsigned mask_i = rowact ? smask[i] : 0u;
    float hc1 = __popc(mask_i) * (1.0f / S);
    unsigned extra = (lane == 0 || !rowact) ? 0u : (mask_i & ~1u);

    // outer-invariant exponent bases (F reconstructed from Earg at the end)
    float Earg[MN], Fbase;
    {
        int id = ids[i];
        float xs = g_xsq[id];
        const float2* pm2 = (const float2*)(g_Pm + (size_t)id*TM + t*MN);
        float pmv[MN];
        #pragma unroll
        for (int h = 0; h < 5; h++) { float2 p = __ldg(&pm2[h]); pmv[2*h] = p.x; pmv[2*h+1] = p.y; }
        float M0 = xs + sF2[t][0] + pmv[0];
        Fbase = oma * M0;
        #pragma unroll
        for (int l = 0; l < MN; l++) {
            float Ml = xs + sF2[t][l] + pmv[l];
            float hh = hc1 + shC2[t][l];
            Earg[l] = rowact ? (oma*(M0 - Ml) - 2.f*alpha*hh) * cE : -1000.f;
        }
    }
    float qcol = __ldg(&g_q[t*MN + (colact ? lane : 0)]);

    // K = q/S (w pre-folded); v = 1 on column lanes. G = K .* v^T (rows x cols)
    float K[MN];
    #pragma unroll
    for (int l = 0; l < MN; l++) K[l] = rowact ? __ldg(&g_q[t*MN + l]) * (1.0f/S) : 0.f;
    float v = 1.0f;

    for (int it = 0; it <= N_OUTER; it++) {
        // gather v vector (only outer start; shared by H0/extras/final)
        float vv[MN];
        #pragma unroll
        for (int l = 0; l < MN; l++) vv[l] = __shfl_sync(FULLMASK, v, l);

        // ---- H0 only (column-marginal identity) ----
        float g0[MN];
        #pragma unroll
        for (int k = 0; k < MN; k++) g0[k] = __shfl_sync(FULLMASK, K[k], 0) * vv[k];
        if (colact) {
            float4 c0 = *(const float4*)&sC2[t][lane][0];
            float4 c1 = *(const float4*)&sC2[t][lane][4];
            float2 c2 = *(const float2*)&sC2[t][lane][8];
            h0buf[t][lane] = g0[0]*c0.x + g0[1]*c0.y + g0[2]*c0.z + g0[3]*c0.w
                           + g0[4]*c1.x + g0[5]*c1.y + g0[6]*c1.z + g0[7]*c1.w
                           + g0[8]*c2.x + g0[9]*c2.y;
        }
        __syncwarp();
        float A[MN];
        {
            float4 a0 = *(const float4*)&h0buf[t][0];
            float4 a1 = *(const float4*)&h0buf[t][4];
            float2 a2 = *(const float2*)&h0buf[t][8];
            A[0]=a0.x; A[1]=a0.y; A[2]=a0.z; A[3]=a0.w;
            A[4]=a1.x; A[5]=a1.y; A[6]=a1.z; A[7]=a1.w;
            A[8]=a2.x; A[9]=a2.y;
        }
        if (lane == 0) {
            float4 q0v = *(const float4*)&sHq[t][0];
            float4 q1v = *(const float4*)&sHq[t][4];
            float2 q2v = *(const float2*)&sHq[t][8];
            A[0]=q0v.x-A[0]; A[1]=q0v.y-A[1]; A[2]=q0v.z-A[2]; A[3]=q0v.w-A[3];
            A[4]=q1v.x-A[4]; A[5]=q1v.y-A[5]; A[6]=q1v.z-A[6]; A[7]=q1v.w-A[7];
            A[8]=q2v.x-A[8]; A[9]=q2v.y-A[9];
        }
        // ---- rare extras: uniform union loop, H_j computed once by col lanes
        unsigned U = __reduce_or_sync(FULLMASK, extra);
        while (U) {
            int j = __ffs(U) - 1;
            U &= U - 1u;
            float gj[MN];
            #pragma unroll
            for (int k = 0; k < MN; k++) gj[k] = __shfl_sync(FULLMASK, K[k], j) * vv[k];
            __syncwarp();                 // all reads of previous h0buf done
            if (colact) {
                float4 c0 = *(const float4*)&sC2[t][lane][0];
                float4 c1 = *(const float4*)&sC2[t][lane][4];
                float2 c2 = *(const float2*)&sC2[t][lane][8];
                h0buf[t][lane] = gj[0]*c0.x + gj[1]*c0.y + gj[2]*c0.z + gj[3]*c0.w
                               + gj[4]*c1.x + gj[5]*c1.y + gj[6]*c1.z + gj[7]*c1.w
                               + gj[8]*c2.x + gj[9]*c2.y;
            }
            __syncwarp();
            bool add = (extra >> j) & 1u;
            float4 a0 = *(const float4*)&h0buf[t][0];
            float4 a1 = *(const float4*)&h0buf[t][4];
            float2 a2 = *(const float2*)&h0buf[t][8];
            if (add) {
                A[0]+=a0.x; A[1]+=a0.y; A[2]+=a0.z; A[3]+=a0.w;
                A[4]+=a1.x; A[5]+=a1.y; A[6]+=a1.z; A[7]+=a1.w;
                A[8]+=a2.x; A[9]+=a2.y;
            }
        }

        if (it == N_OUTER) {
            float acc = 0.f;
            #pragma unroll
            for (int l = 0; l < MN; l++) {
                float hh = hc1 + shC2[t][l];
                float Fl = Fbase - Earg[l]*invcE - alpha*hh;
                acc += K[l]*vv[l] * fmaf(m2a, A[l], Fl);
            }
            acc += __shfl_xor_sync(FULLMASK, acc, 16);
            acc += __shfl_xor_sync(FULLMASK, acc, 8);
            acc += __shfl_xor_sync(FULLMASK, acc, 4);
            acc += __shfl_xor_sync(FULLMASK, acc, 2);
            acc += __shfl_xor_sync(FULLMASK, acc, 1);
            if (lane == 0) out[n*T + t] = acc;
            return;
        }

        // ---- K = exp2(Earg + c3*A) (row-shifted kernel) ----
        #pragma unroll
        for (int l = 0; l < MN; l++) K[l] = ex2(fmaf(c3, A[l], Earg[l]));

        // ---- transpose K (conflict-free stride-11 smem) ----
        __syncwarp();                    // h0buf/kbuf phase boundary
        if (rowact) {
            #pragma unroll
            for (int l = 0; l < MN; l++) kbuf[t][lane][l] = K[l];
        }
        __syncwarp();
        float KT[S];
        if (colact) {
            #pragma unroll
            for (int ii = 0; ii < S; ii++) KT[ii] = kbuf[t][ii][lane];
        }

        // ---- Sinkhorn in scaling domain (shfl gathers, regs only) ----
        float w;
        {   // iteration 1 peeled: v == 1
            float rs = K[0]+K[1]+K[2]+K[3]+K[4]+K[5]+K[6]+K[7]+K[8]+K[9];
            w = rowact ? __fdividef(1.0f / S, rs) : 0.f;
            float cs = 0.f;
            #pragma unroll
            for (int ii = 0; ii < S; ii++) cs += KT[ii] * __shfl_sync(FULLMASK, w, ii);
            if (colact) v = __fdividef(qcol, cs);
        }
        #pragma unroll
        for (int si = 1; si < N_SINK; si++) {
            float rs = 0.f;
            #pragma unroll
            for (int l = 0; l < MN; l++) rs += K[l] * __shfl_sync(FULLMASK, v, l);
            w = rowact ? __fdividef(1.0f / S, rs) : 0.f;
            float cs = 0.f;
            #pragma unroll
            for (int ii = 0; ii < S; ii++) cs += KT[ii] * __shfl_sync(FULLMASK, w, ii);
            if (colact) v = __fdividef(qcol, cs);
        }
        // fold w into K: G = K .* v^T next outer
        #pragma unroll
        for (int l = 0; l < MN; l++) K[l] *= w;
    }
}

// ---------------- launch ----------------------------------------------------
extern "C" void kernel_launch(void* const* d_in, const int* in_sizes, int n_in,
                              void* d_out, int out_size) {
    const float* x      = (const float*)d_in[0];
    const int*   edge   = (const int*)  d_in[1];
    const float* tmpl   = (const float*)d_in[2];
    const float* tf     = (const float*)d_in[3];
    const float* q0     = (const float*)d_in[4];
    const float* alpha0 = (const float*)d_in[5];
    const int*   dst    = edge + N_NODES*DEG;
    float* out = (float*)d_out;

    pm_pre_kernel<<<N_NODES/NPB, 256>>>(x, tf, tmpl, q0, alpha0);
    ltfgw_kernel<<<N_NODES, 320>>>(dst, out);
}

// round 9
// speedup vs baseline: 2.1172x; 1.1368x over previous
#include <cuda_runtime.h>
#include <math.h>

#define N_NODES 5000
#define DEG 16
#define S 17
#define T 10
#define MN 10
#define D 128
#define EPS 0.1f
#define N_OUTER 3
#define N_SINK 5
#define TM 100
#define NPB 10
#define LOG2E 1.4426950408889634f
#define LN2 0.6931471805599453f
#define FULLMASK 0xffffffffu

__device__ __forceinline__ float ex2(float x) {
    float r; asm("ex2.approx.ftz.f32 %0, %1;" : "=f"(r) : "f"(x)); return r;
}

// ---------------- device-global precomputed state / scratch ----------------
__device__ float g_alpha;
__device__ float g_C2[T*MN*MN];
__device__ float g_q[T*MN];
__device__ float g_hC2[T*MN];
__device__ float g_Hq[T*MN];
__device__ float g_f2sq[T*MN];
__device__ float g_Pm[(size_t)N_NODES * TM];   // -2<x_n,F2_tm>
__device__ float g_xsq[N_NODES];

// ---------------- kernel 1: Pm GEMM + fused precompute (block 0) ----------
__global__ __launch_bounds__(256) void pm_pre_kernel(const float* __restrict__ x,
                                                     const float* __restrict__ tf,
                                                     const float* __restrict__ tmpl,
                                                     const float* __restrict__ q0,
                                                     const float* __restrict__ alpha0) {
    __shared__ __align__(16) float4 sx4[NPB][D/4];
    int base = blockIdx.x * NPB;
    int tid = threadIdx.x;

    for (int idx = tid; idx < NPB*(D/4); idx += 256) {
        int r = idx / (D/4), c = idx % (D/4);
        sx4[r][c] = ((const float4*)(x + (size_t)(base + r)*D))[c];
    }
    __syncthreads();
    if (tid < NPB) {
        float s = 0.f;
        #pragma unroll 8
        for (int d = 0; d < D/4; d++) {
            float4 v = sx4[tid][d];
            s += v.x*v.x + v.y*v.y + v.z*v.z + v.w*v.w;
        }
        g_xsq[base + tid] = s;
    }
    if (tid < NPB * (TM/4)) {
        int nl = tid % NPB, tm0 = (tid / NPB) * 4;
        const float4* b0 = (const float4*)(tf + (size_t)(tm0+0)*D);
        const float4* b1 = (const float4*)(tf + (size_t)(tm0+1)*D);
        const float4* b2 = (const float4*)(tf + (size_t)(tm0+2)*D);
        const float4* b3 = (const float4*)(tf + (size_t)(tm0+3)*D);
        float a0=0.f, a1=0.f, a2=0.f, a3=0.f;
        #pragma unroll 8
        for (int d = 0; d < D/4; d++) {
            float4 av = sx4[nl][d];
            float4 r0 = b0[d], r1 = b1[d], r2 = b2[d], r3 = b3[d];
            a0 += av.x*r0.x + av.y*r0.y + av.z*r0.z + av.w*r0.w;
            a1 += av.x*r1.x + av.y*r1.y + av.z*r1.z + av.w*r1.w;
            a2 += av.x*r2.x + av.y*r2.y + av.z*r2.z + av.w*r2.w;
            a3 += av.x*r3.x + av.y*r3.y + av.z*r3.z + av.w*r3.w;
        }
        size_t o = (size_t)(base + nl)*TM + tm0;
        g_Pm[o+0] = -2.f*a0; g_Pm[o+1] = -2.f*a1;
        g_Pm[o+2] = -2.f*a2; g_Pm[o+3] = -2.f*a3;
    }

    if (blockIdx.x == 0) {
        if (tid == 0) g_alpha = 1.0f / (1.0f + expf(-alpha0[0]));
        if (tid < T) {
            float mx = -1e30f;
            for (int m = 0; m < MN; m++) mx = fmaxf(mx, q0[tid*MN + m]);
            float s = 0.f, e[MN];
            for (int m = 0; m < MN; m++) { e[m] = expf(q0[tid*MN + m] - mx); s += e[m]; }
            for (int m = 0; m < MN; m++) g_q[tid*MN + m] = e[m] / s;
        }
        if (tid < T*MN) {
            int t = tid / MN, j = tid % MN;
            float mx = -1e30f;
            for (int i = 0; i < MN; i++) mx = fmaxf(mx, tmpl[(t*MN + i)*MN + j]);
            float s = 0.f, e[MN];
            for (int i = 0; i < MN; i++) { e[i] = expf(tmpl[(t*MN + i)*MN + j] - mx); s += e[i]; }
            for (int i = 0; i < MN; i++) g_C2[(t*MN + i)*MN + j] = e[i] / s;
        }
        if (tid < T*MN) {
            float s = 0.f;
            const float4* row = (const float4*)(tf + (size_t)tid * D);
            #pragma unroll 8
            for (int d = 0; d < D/4; d++) {
                float4 v = row[d];
                s += v.x*v.x + v.y*v.y + v.z*v.z + v.w*v.w;
            }
            g_f2sq[tid] = s;
        }
        __syncthreads();
        if (tid < T*MN) {
            int t = tid / MN, l = tid % MN;
            float s = 0.f, hq = 0.f;
            for (int k = 0; k < MN; k++) {
                float c = g_C2[(t*MN + l)*MN + k];
                float qq = g_q[t*MN + k];
                s += c * c * qq;
                hq += c * qq;
            }
            g_hC2[tid] = s;
            g_Hq[tid]  = hq;
        }
    }
}

// ---------------- kernel 2: FGW — broadcast-smem comm, near-zero shfl ------
__global__ __launch_bounds__(320, 2) void ltfgw_kernel(const int* __restrict__ dst,
                                                       float* __restrict__ out) {
    __shared__ __align__(16) float sC2[T][MN][12];   // zero-padded rows
    __shared__ __align__(16) float krows[T][S][12];  // K rows (unfolded), aligned
    __shared__ __align__(16) float vbuf[T][12];
    __shared__ __align__(16) float wbuf[T][20];
    __shared__ __align__(16) float h0buf[T][12];
    __shared__ __align__(16) float sHq[T][12];
    __shared__ __align__(16) float shC2[T][12];
    __shared__ float sF2[T][MN];
    __shared__ unsigned smask[S];
    __shared__ int ids[S];

    int n = blockIdx.x, tid = threadIdx.x;

    if (tid < S) {
        ids[tid] = (tid == 0) ? n : dst[n*DEG + tid - 1];
        smask[tid] = 0u;
    }
    for (int idx = tid; idx < T*MN*12; idx += 320) {
        int t0 = idx / (MN*12), rem = idx % (MN*12);
        int l0 = rem / 12, k0 = rem % 12;
        ((float*)sC2)[idx] = (k0 < MN) ? g_C2[(t0*MN + l0)*MN + k0] : 0.f;
    }
    for (int idx = tid; idx < T*MN; idx += 320) {
        int t0 = idx / MN, l0 = idx % MN;
        sHq[t0][l0]  = g_Hq[idx];
        shC2[t0][l0] = g_hC2[idx];
        sF2[t0][l0]  = g_f2sq[idx];
    }
    __syncthreads();

    for (int e = tid; e < S*DEG; e += 320) {
        int a = e / DEG, k = e % DEG;
        int nb = dst[ids[a]*DEG + k];
        #pragma unroll
        for (int b = 0; b < S; b++) {
            if (ids[b] == nb) { atomicOr(&smask[a], 1u << b); atomicOr(&smask[b], 1u << a); }
        }
    }
    __syncthreads();
    if (tid < S) smask[tid] &= ~(1u << tid);
    __syncthreads();

    const float alpha = g_alpha;
    const float oma = 1.0f - alpha;
    const float cE = (1.0f/EPS) * LOG2E;
    const float invcE = EPS * LN2;
    const float c3 = 4.0f * alpha * (1.0f/EPS) * LOG2E;
    const float m2a = -2.0f * alpha;

    int t = tid >> 5, lane = tid & 31;
    bool rowact = lane < S;
    bool colact = lane < MN;
    int i = rowact ? lane : 0;
    unsigned mask_i = rowact ? smask[i] : 0u;
    float hc1 = __popc(mask_i) * (1.0f / S);
    unsigned extra = (lane == 0 || !rowact) ? 0u : (mask_i & ~1u);
    unsigned Uall = __reduce_or_sync(FULLMASK, extra);

    // outer-invariant exponent bases (F reconstructed from Earg at the end)
    float Earg[MN], Fbase;
    {
        int id = ids[i];
        float xs = g_xsq[id];
        const float2* pm2 = (const float2*)(g_Pm + (size_t)id*TM + t*MN);
        float pmv[MN];
        #pragma unroll
        for (int h = 0; h < 5; h++) { float2 p = __ldg(&pm2[h]); pmv[2*h] = p.x; pmv[2*h+1] = p.y; }
        float M0 = xs + sF2[t][0] + pmv[0];
        Fbase = oma * M0;
        #pragma unroll
        for (int l = 0; l < MN; l++) {
            float Ml = xs + sF2[t][l] + pmv[l];
            float hh = hc1 + shC2[t][l];
            Earg[l] = rowact ? (oma*(M0 - Ml) - 2.f*alpha*hh) * cE : -1000.f;
        }
    }
    float qcol = __ldg(&g_q[t*MN + (colact ? lane : 0)]);

    // init: K = q (unfolded), w = 1/S, v = 1  →  G0 = p q^T
    float K[MN], w = rowact ? (1.0f / S) : 0.f;
    #pragma unroll
    for (int l = 0; l < MN; l++) K[l] = rowact ? __ldg(&g_q[t*MN + l]) : 0.f;
    if (rowact) {
        *(float4*)&krows[t][lane][0] = make_float4(K[0],K[1],K[2],K[3]);
        *(float4*)&krows[t][lane][4] = make_float4(K[4],K[5],K[6],K[7]);
        *(float2*)&krows[t][lane][8] = make_float2(K[8],K[9]);
        wbuf[t][lane] = w;
    }
    if (colact) vbuf[t][lane] = 1.0f;
    __syncwarp();

    for (int it = 0; it <= N_OUTER; it++) {
        // ---- H0 (column-marginal identity): col lane l computes H0[l] ----
        float vc[MN];   // v vector, broadcast loaded (used by col lanes)
        {
            float4 a0 = *(const float4*)&vbuf[t][0];
            float4 a1 = *(const float4*)&vbuf[t][4];
            float2 a2 = *(const float2*)&vbuf[t][8];
            vc[0]=a0.x; vc[1]=a0.y; vc[2]=a0.z; vc[3]=a0.w;
            vc[4]=a1.x; vc[5]=a1.y; vc[6]=a1.z; vc[7]=a1.w;
            vc[8]=a2.x; vc[9]=a2.y;
        }
        __syncwarp();   // any previous h0buf readers done
        if (colact) {
            float w0 = wbuf[t][0];
            float4 k0 = *(const float4*)&krows[t][0][0];
            float4 k1 = *(const float4*)&krows[t][0][4];
            float2 k2 = *(const float2*)&krows[t][0][8];
            float4 c0 = *(const float4*)&sC2[t][lane][0];
            float4 c1 = *(const float4*)&sC2[t][lane][4];
            float2 c2 = *(const float2*)&sC2[t][lane][8];
            float h = k0.x*vc[0]*c0.x + k0.y*vc[1]*c0.y + k0.z*vc[2]*c0.z + k0.w*vc[3]*c0.w
                    + k1.x*vc[4]*c1.x + k1.y*vc[5]*c1.y + k1.z*vc[6]*c1.z + k1.w*vc[7]*c1.w
                    + k2.x*vc[8]*c2.x + k2.y*vc[9]*c2.y;
            h0buf[t][lane] = h * w0;
        }
        __syncwarp();
        float A[MN];
        {
            float4 a0 = *(const float4*)&h0buf[t][0];
            float4 a1 = *(const float4*)&h0buf[t][4];
            float2 a2 = *(const float2*)&h0buf[t][8];
            A[0]=a0.x; A[1]=a0.y; A[2]=a0.z; A[3]=a0.w;
            A[4]=a1.x; A[5]=a1.y; A[6]=a1.z; A[7]=a1.w;
            A[8]=a2.x; A[9]=a2.y;
        }
        if (lane == 0) {
            float4 q0v = *(const float4*)&sHq[t][0];
            float4 q1v = *(const float4*)&sHq[t][4];
            float2 q2v = *(const float2*)&sHq[t][8];
            A[0]=q0v.x-A[0]; A[1]=q0v.y-A[1]; A[2]=q0v.z-A[2]; A[3]=q0v.w-A[3];
            A[4]=q1v.x-A[4]; A[5]=q1v.y-A[5]; A[6]=q1v.z-A[6]; A[7]=q1v.w-A[7];
            A[8]=q2v.x-A[8]; A[9]=q2v.y-A[9];
        }
        // ---- rare extras via krows broadcast reads ----
        unsigned U = Uall;
        while (U) {
            int j = __ffs(U) - 1;
            U &= U - 1u;
            __syncwarp();
            if (colact) {
                float wj = wbuf[t][j];
                float4 k0 = *(const float4*)&krows[t][j][0];
                float4 k1 = *(const float4*)&krows[t][j][4];
                float2 k2 = *(const float2*)&krows[t][j][8];
                float4 c0 = *(const float4*)&sC2[t][lane][0];
                float4 c1 = *(const float4*)&sC2[t][lane][4];
                float2 c2 = *(const float2*)&sC2[t][lane][8];
                float h = k0.x*vc[0]*c0.x + k0.y*vc[1]*c0.y + k0.z*vc[2]*c0.z + k0.w*vc[3]*c0.w
                        + k1.x*vc[4]*c1.x + k1.y*vc[5]*c1.y + k1.z*vc[6]*c1.z + k1.w*vc[7]*c1.w
                        + k2.x*vc[8]*c2.x + k2.y*vc[9]*c2.y;
                h0buf[t][lane] = h * wj;
            }
            __syncwarp();
            if ((extra >> j) & 1u) {
                float4 a0 = *(const float4*)&h0buf[t][0];
                float4 a1 = *(const float4*)&h0buf[t][4];
                float2 a2 = *(const float2*)&h0buf[t][8];
                A[0]+=a0.x; A[1]+=a0.y; A[2]+=a0.z; A[3]+=a0.w;
                A[4]+=a1.x; A[5]+=a1.y; A[6]+=a1.z; A[7]+=a1.w;
                A[8]+=a2.x; A[9]+=a2.y;
            }
        }

        if (it == N_OUTER) {
            // G row i = w * K[l] * v[l]
            float acc = 0.f;
            #pragma unroll
            for (int l = 0; l < MN; l++) {
                float hh = hc1 + shC2[t][l];
                float Fl = Fbase - Earg[l]*invcE - alpha*hh;
                acc += w * K[l] * vc[l] * fmaf(m2a, A[l], Fl);
            }
            acc += __shfl_xor_sync(FULLMASK, acc, 16);
            acc += __shfl_xor_sync(FULLMASK, acc, 8);
            acc += __shfl_xor_sync(FULLMASK, acc, 4);
            acc += __shfl_xor_sync(FULLMASK, acc, 2);
            acc += __shfl_xor_sync(FULLMASK, acc, 1);
            if (lane == 0) out[n*T + t] = acc;
            return;
        }

        // ---- K = exp2(Earg + c3*A) ----
        #pragma unroll
        for (int l = 0; l < MN; l++) K[l] = ex2(fmaf(c3, A[l], Earg[l]));

        // store K rows (unfolded) for next outer's H phase + KT transpose
        __syncwarp();
        if (rowact) {
            *(float4*)&krows[t][lane][0] = make_float4(K[0],K[1],K[2],K[3]);
            *(float4*)&krows[t][lane][4] = make_float4(K[4],K[5],K[6],K[7]);
            *(float2*)&krows[t][lane][8] = make_float2(K[8],K[9]);
        }
        __syncwarp();
        float KT[S];
        if (colact) {
            #pragma unroll
            for (int ii = 0; ii < S; ii++) KT[ii] = krows[t][ii][lane];
        }

        // ---- Sinkhorn: v/w through broadcast smem ----
        {   // iter 1 peeled: v == 1
            float rs = K[0]+K[1]+K[2]+K[3]+K[4]+K[5]+K[6]+K[7]+K[8]+K[9];
            w = rowact ? __fdividef(1.0f / S, rs) : 0.f;
            if (rowact) wbuf[t][lane] = w;
            __syncwarp();
            if (colact) {
                float4 w0 = *(const float4*)&wbuf[t][0];
                float4 w1 = *(const float4*)&wbuf[t][4];
                float4 w2 = *(const float4*)&wbuf[t][8];
                float4 w3 = *(const float4*)&wbuf[t][12];
                float  w4 = wbuf[t][16];
                float cs = KT[0]*w0.x + KT[1]*w0.y + KT[2]*w0.z + KT[3]*w0.w
                         + KT[4]*w1.x + KT[5]*w1.y + KT[6]*w1.z + KT[7]*w1.w
                         + KT[8]*w2.x + KT[9]*w2.y + KT[10]*w2.z + KT[11]*w2.w
                         + KT[12]*w3.x + KT[13]*w3.y + KT[14]*w3.z + KT[15]*w3.w
                         + KT[16]*w4;
                vbuf[t][lane] = __fdividef(qcol, cs);
            }
            __syncwarp();
        }
        #pragma unroll
        for (int si = 1; si < N_SINK; si++) {
            float4 b0 = *(const float4*)&vbuf[t][0];
            float4 b1 = *(const float4*)&vbuf[t][4];
            float2 b2 = *(const float2*)&vbuf[t][8];
            float rs = K[0]*b0.x + K[1]*b0.y + K[2]*b0.z + K[3]*b0.w
                     + K[4]*b1.x + K[5]*b1.y + K[6]*b1.z + K[7]*b1.w
                     + K[8]*b2.x + K[9]*b2.y;
            w = rowact ? __fdividef(1.0f / S, rs) : 0.f;
            if (rowact) wbuf[t][lane] = w;
            __syncwarp();
            if (colact) {
                float4 w0 = *(const float4*)&wbuf[t][0];
                float4 w1 = *(const float4*)&wbuf[t][4];
                float4 w2 = *(const float4*)&wbuf[t][8];
                float4 w3 = *(const float4*)&wbuf[t][12];
                float  w4 = wbuf[t][16];
                float cs = KT[0]*w0.x + KT[1]*w0.y + KT[2]*w0.z + KT[3]*w0.w
                         + KT[4]*w1.x + KT[5]*w1.y + KT[6]*w1.z + KT[7]*w1.w
                         + KT[8]*w2.x + KT[9]*w2.y + KT[10]*w2.z + KT[11]*w2.w
                         + KT[12]*w3.x + KT[13]*w3.y + KT[14]*w3.z + KT[15]*w3.w
                         + KT[16]*w4;
                vbuf[t][lane] = __fdividef(qcol, cs);
            }
            __syncwarp();
        }
        // K stays unfolded; w (regs + wbuf) and v (vbuf) carry the scaling.
    }
}

// ---------------- launch ----------------------------------------------------
extern "C" void kernel_launch(void* const* d_in, const int* in_sizes, int n_in,
                              void* d_out, int out_size) {
    const float* x      = (const float*)d_in[0];
    const int*   edge   = (const int*)  d_in[1];
    const float* tmpl   = (const float*)d_in[2];
    const float* tf     = (const float*)d_in[3];
    const float* q0     = (const float*)d_in[4];
    const float* alpha0 = (const float*)d_in[5];
    const int*   dst    = edge + N_NODES*DEG;
    float* out = (float*)d_out;

    pm_pre_kernel<<<N_NODES/NPB, 256>>>(x, tf, tmpl, q0, alpha0);
    ltfgw_kernel<<<N_NODES, 320>>>(dst, out);
}

// round 10
// speedup vs baseline: 2.6193x; 1.2372x over previous
#include <cuda_runtime.h>
#include <math.h>

#define N_NODES 5000
#define DEG 16
#define S 17
#define T 10
#define MN 10
#define D 128
#define EPS 0.1f
#define N_OUTER 3
#define N_SINK 5
#define TM 100
#define NPB 20
#define LOG2E 1.4426950408889634f
#define LN2 0.6931471805599453f
#define FULLMASK 0xffffffffu

__device__ __forceinline__ float ex2(float x) {
    float r; asm("ex2.approx.ftz.f32 %0, %1;" : "=f"(r) : "f"(x)); return r;
}

// ---------------- device-global precomputed state / scratch ----------------
__device__ float g_alpha;
__device__ float g_C2[T*MN*MN];
__device__ float g_q[T*MN];
__device__ float g_hC2[T*MN];
__device__ float g_Hq[T*MN];
__device__ float g_f2sq[T*MN];
__device__ float g_Pm[(size_t)N_NODES * TM];   // -2<x_n,F2_tm>
__device__ float g_xsq[N_NODES];

// ---------------- kernel 1: Pm GEMM + fused precompute (block 0) ----------
__global__ __launch_bounds__(512) void pm_pre_kernel(const float* __restrict__ x,
                                                     const float* __restrict__ tf,
                                                     const float* __restrict__ tmpl,
                                                     const float* __restrict__ q0,
                                                     const float* __restrict__ alpha0) {
    __shared__ __align__(16) float4 sx4[NPB][D/4 + 1];   // padded: avoid bank-group 0 pileup
    int base = blockIdx.x * NPB;
    int tid = threadIdx.x;

    for (int idx = tid; idx < NPB*(D/4); idx += 512) {
        int r = idx / (D/4), c = idx % (D/4);
        sx4[r][c] = ((const float4*)(x + (size_t)(base + r)*D))[c];
    }
    __syncthreads();
    if (tid < NPB) {
        float s = 0.f;
        #pragma unroll 8
        for (int d = 0; d < D/4; d++) {
            float4 v = sx4[tid][d];
            s += v.x*v.x + v.y*v.y + v.z*v.z + v.w*v.w;
        }
        g_xsq[base + tid] = s;
    }
    if (tid < NPB * (TM/4)) {
        int nl = tid % NPB, tm0 = (tid / NPB) * 4;
        const float4* b0 = (const float4*)(tf + (size_t)(tm0+0)*D);
        const float4* b1 = (const float4*)(tf + (size_t)(tm0+1)*D);
        const float4* b2 = (const float4*)(tf + (size_t)(tm0+2)*D);
        const float4* b3 = (const float4*)(tf + (size_t)(tm0+3)*D);
        float a0=0.f, a1=0.f, a2=0.f, a3=0.f;
        #pragma unroll 8
        for (int d = 0; d < D/4; d++) {
            float4 av = sx4[nl][d];
            float4 r0 = b0[d], r1 = b1[d], r2 = b2[d], r3 = b3[d];
            a0 += av.x*r0.x + av.y*r0.y + av.z*r0.z + av.w*r0.w;
            a1 += av.x*r1.x + av.y*r1.y + av.z*r1.z + av.w*r1.w;
            a2 += av.x*r2.x + av.y*r2.y + av.z*r2.z + av.w*r2.w;
            a3 += av.x*r3.x + av.y*r3.y + av.z*r3.z + av.w*r3.w;
        }
        size_t o = (size_t)(base + nl)*TM + tm0;
        g_Pm[o+0] = -2.f*a0; g_Pm[o+1] = -2.f*a1;
        g_Pm[o+2] = -2.f*a2; g_Pm[o+3] = -2.f*a3;
    }

    if (blockIdx.x == 0) {
        if (tid == 0) g_alpha = 1.0f / (1.0f + expf(-alpha0[0]));
        if (tid < T) {
            float mx = -1e30f;
            for (int m = 0; m < MN; m++) mx = fmaxf(mx, q0[tid*MN + m]);
            float s = 0.f, e[MN];
            for (int m = 0; m < MN; m++) { e[m] = expf(q0[tid*MN + m] - mx); s += e[m]; }
            for (int m = 0; m < MN; m++) g_q[tid*MN + m] = e[m] / s;
        }
        if (tid < T*MN) {
            int t = tid / MN, j = tid % MN;
            float mx = -1e30f;
            for (int i = 0; i < MN; i++) mx = fmaxf(mx, tmpl[(t*MN + i)*MN + j]);
            float s = 0.f, e[MN];
            for (int i = 0; i < MN; i++) { e[i] = expf(tmpl[(t*MN + i)*MN + j] - mx); s += e[i]; }
            for (int i = 0; i < MN; i++) g_C2[(t*MN + i)*MN + j] = e[i] / s;
        }
        if (tid < T*MN) {
            float s = 0.f;
            const float4* row = (const float4*)(tf + (size_t)tid * D);
            #pragma unroll 8
            for (int d = 0; d < D/4; d++) {
                float4 v = row[d];
                s += v.x*v.x + v.y*v.y + v.z*v.z + v.w*v.w;
            }
            g_f2sq[tid] = s;
        }
        __syncthreads();
        if (tid < T*MN) {
            int t = tid / MN, l = tid % MN;
            float s = 0.f, hq = 0.f;
            for (int k = 0; k < MN; k++) {
                float c = g_C2[(t*MN + l)*MN + k];
                float qq = g_q[t*MN + k];
                s += c * c * qq;
                hq += c * qq;
            }
            g_hC2[tid] = s;
            g_Hq[tid]  = hq;
        }
    }
}

// ---------------- kernel 2: FGW — low-register, G rows in smem -------------
__global__ __launch_bounds__(320, 3) void ltfgw_kernel(const int* __restrict__ dst,
                                                       float* __restrict__ out) {
    __shared__ __align__(16) float sC2[T][MN][12];    // zero-padded rows
    __shared__ __align__(16) float grows[T][S][12];   // G rows; transiently K rows
    __shared__ __align__(16) float eargs[T][S][12];   // outer-invariant exponent bases
    __shared__ __align__(16) float vbuf[T][12];
    __shared__ __align__(16) float wbuf[T][20];
    __shared__ __align__(16) float h0buf[T][12];
    __shared__ __align__(16) float sHq[T][12];
    __shared__ __align__(16) float shC2[T][12];
    __shared__ __align__(16) float sF2[T][12];
    __shared__ __align__(16) float sq_[T][12];
    __shared__ unsigned smask[S];
    __shared__ int ids[S];

    int n = blockIdx.x, tid = threadIdx.x;

    if (tid < S) {
        ids[tid] = (tid == 0) ? n : dst[n*DEG + tid - 1];
        smask[tid] = 0u;
    }
    for (int idx = tid; idx < T*MN*12; idx += 320) {
        int t0 = idx / (MN*12), rem = idx % (MN*12);
        int l0 = rem / 12, k0 = rem % 12;
        ((float*)sC2)[idx] = (k0 < MN) ? g_C2[(t0*MN + l0)*MN + k0] : 0.f;
    }
    for (int idx = tid; idx < T*MN; idx += 320) {
        int t0 = idx / MN, l0 = idx % MN;
        sHq[t0][l0]  = g_Hq[idx];
        shC2[t0][l0] = g_hC2[idx];
        sF2[t0][l0]  = g_f2sq[idx];
        sq_[t0][l0]  = g_q[idx];
    }
    __syncthreads();

    for (int e = tid; e < S*DEG; e += 320) {
        int a = e / DEG, k = e % DEG;
        int nb = dst[ids[a]*DEG + k];
        #pragma unroll
        for (int b = 0; b < S; b++) {
            if (ids[b] == nb) { atomicOr(&smask[a], 1u << b); atomicOr(&smask[b], 1u << a); }
        }
    }
    __syncthreads();
    if (tid < S) smask[tid] &= ~(1u << tid);
    __syncthreads();

    const float alpha = g_alpha;
    const float oma = 1.0f - alpha;
    const float cE = (1.0f/EPS) * LOG2E;
    const float invcE = EPS * LN2;
    const float c3 = 4.0f * alpha * (1.0f/EPS) * LOG2E;
    const float m2a = -2.0f * alpha;

    int t = tid >> 5, lane = tid & 31;
    bool rowact = lane < S;
    bool colact = lane < MN;
    unsigned mask_i = rowact ? smask[lane] : 0u;
    float hc1 = __popc(mask_i) * (1.0f / S);
    unsigned extra = (lane == 0 || !rowact) ? 0u : (mask_i & ~1u);
    unsigned Uall = __reduce_or_sync(FULLMASK, extra);

    // setup: Earg rows + G0 rows into smem (row lanes only)
    float Fbase = 0.f;
    if (rowact) {
        int id = ids[lane];
        float xs = g_xsq[id];
        const float2* pm2 = (const float2*)(g_Pm + (size_t)id*TM + t*MN);
        float pmv[MN];
        #pragma unroll
        for (int h = 0; h < 5; h++) { float2 p = __ldg(&pm2[h]); pmv[2*h] = p.x; pmv[2*h+1] = p.y; }
        float M0 = xs + sF2[t][0] + pmv[0];
        Fbase = oma * M0;
        float e[MN];
        #pragma unroll
        for (int l = 0; l < MN; l++) {
            float Ml = xs + sF2[t][l] + pmv[l];
            float hh = hc1 + shC2[t][l];
            e[l] = (oma*(M0 - Ml) - 2.f*alpha*hh) * cE;
        }
        *(float4*)&eargs[t][lane][0] = make_float4(e[0],e[1],e[2],e[3]);
        *(float4*)&eargs[t][lane][4] = make_float4(e[4],e[5],e[6],e[7]);
        *(float2*)&eargs[t][lane][8] = make_float2(e[8],e[9]);
        // G0 row = p q^T row = q/S
        float4 q0v = *(const float4*)&sq_[t][0];
        float4 q1v = *(const float4*)&sq_[t][4];
        float2 q2v = *(const float2*)&sq_[t][8];
        *(float4*)&grows[t][lane][0] = make_float4(q0v.x*(1.f/S), q0v.y*(1.f/S), q0v.z*(1.f/S), q0v.w*(1.f/S));
        *(float4*)&grows[t][lane][4] = make_float4(q1v.x*(1.f/S), q1v.y*(1.f/S), q1v.z*(1.f/S), q1v.w*(1.f/S));
        *(float2*)&grows[t][lane][8] = make_float2(q2v.x*(1.f/S), q2v.y*(1.f/S));
    }
    float qcol = sq_[t][colact ? lane : 0];
    int ei = rowact ? lane : 0;     // own-row index (clamped)
    int lcol = colact ? lane : 0;   // own-col index (clamped)

    for (int it = 0; it <= N_OUTER; it++) {
        __syncwarp();   // grows stores visible; prior h0buf readers done
        // ---- H0 (column-marginal identity): col lane l computes H0[l] ----
        if (colact) {
            float4 k0 = *(const float4*)&grows[t][0][0];
            float4 k1 = *(const float4*)&grows[t][0][4];
            float2 k2 = *(const float2*)&grows[t][0][8];
            float4 c0 = *(const float4*)&sC2[t][lane][0];
            float4 c1 = *(const float4*)&sC2[t][lane][4];
            float2 c2 = *(const float2*)&sC2[t][lane][8];
            h0buf[t][lane] = k0.x*c0.x + k0.y*c0.y + k0.z*c0.z + k0.w*c0.w
                           + k1.x*c1.x + k1.y*c1.y + k1.z*c1.z + k1.w*c1.w
                           + k2.x*c2.x + k2.y*c2.y;
        }
        __syncwarp();
        float A[MN];
        {
            float4 a0 = *(const float4*)&h0buf[t][0];
            float4 a1 = *(const float4*)&h0buf[t][4];
            float2 a2 = *(const float2*)&h0buf[t][8];
            A[0]=a0.x; A[1]=a0.y; A[2]=a0.z; A[3]=a0.w;
            A[4]=a1.x; A[5]=a1.y; A[6]=a1.z; A[7]=a1.w;
            A[8]=a2.x; A[9]=a2.y;
        }
        if (lane == 0) {
            float4 q0v = *(const float4*)&sHq[t][0];
            float4 q1v = *(const float4*)&sHq[t][4];
            float2 q2v = *(const float2*)&sHq[t][8];
            A[0]=q0v.x-A[0]; A[1]=q0v.y-A[1]; A[2]=q0v.z-A[2]; A[3]=q0v.w-A[3];
            A[4]=q1v.x-A[4]; A[5]=q1v.y-A[5]; A[6]=q1v.z-A[6]; A[7]=q1v.w-A[7];
            A[8]=q2v.x-A[8]; A[9]=q2v.y-A[9];
        }
        // ---- rare extras via grows broadcast reads ----
        unsigned U = Uall;
        while (U) {
            int j = __ffs(U) - 1;
            U &= U - 1u;
            __syncwarp();
            if (colact) {
                float4 k0 = *(const float4*)&grows[t][j][0];
                float4 k1 = *(const float4*)&grows[t][j][4];
                float2 k2 = *(const float2*)&grows[t][j][8];
                float4 c0 = *(const float4*)&sC2[t][lane][0];
                float4 c1 = *(const float4*)&sC2[t][lane][4];
                float2 c2 = *(const float2*)&sC2[t][lane][8];
                h0buf[t][lane] = k0.x*c0.x + k0.y*c0.y + k0.z*c0.z + k0.w*c0.w
                               + k1.x*c1.x + k1.y*c1.y + k1.z*c1.z + k1.w*c1.w
                               + k2.x*c2.x + k2.y*c2.y;
            }
            __syncwarp();
            if ((extra >> j) & 1u) {
                float4 a0 = *(const float4*)&h0buf[t][0];
                float4 a1 = *(const float4*)&h0buf[t][4];
                float2 a2 = *(const float2*)&h0buf[t][8];
                A[0]+=a0.x; A[1]+=a0.y; A[2]+=a0.z; A[3]+=a0.w;
                A[4]+=a1.x; A[5]+=a1.y; A[6]+=a1.z; A[7]+=a1.w;
                A[8]+=a2.x; A[9]+=a2.y;
            }
        }

        if (it == N_OUTER) {
            float acc = 0.f;
            if (rowact) {
                float4 g0 = *(const float4*)&grows[t][lane][0];
                float4 g1 = *(const float4*)&grows[t][lane][4];
                float2 g2 = *(const float2*)&grows[t][lane][8];
                float4 e0 = *(const float4*)&eargs[t][lane][0];
                float4 e1 = *(const float4*)&eargs[t][lane][4];
                float2 e2 = *(const float2*)&eargs[t][lane][8];
                float4 h0 = *(const float4*)&shC2[t][0];
                float4 h1 = *(const float4*)&shC2[t][4];
                float2 h2 = *(const float2*)&shC2[t][8];
                float gg[MN] = {g0.x,g0.y,g0.z,g0.w,g1.x,g1.y,g1.z,g1.w,g2.x,g2.y};
                float ee[MN] = {e0.x,e0.y,e0.z,e0.w,e1.x,e1.y,e1.z,e1.w,e2.x,e2.y};
                float hh[MN] = {h0.x,h0.y,h0.z,h0.w,h1.x,h1.y,h1.z,h1.w,h2.x,h2.y};
                #pragma unroll
                for (int l = 0; l < MN; l++) {
                    float Fl = Fbase - ee[l]*invcE - alpha*(hc1 + hh[l]);
                    acc += gg[l] * fmaf(m2a, A[l], Fl);
                }
            }
            acc += __shfl_xor_sync(FULLMASK, acc, 16);
            acc += __shfl_xor_sync(FULLMASK, acc, 8);
            acc += __shfl_xor_sync(FULLMASK, acc, 4);
            acc += __shfl_xor_sync(FULLMASK, acc, 2);
            acc += __shfl_xor_sync(FULLMASK, acc, 1);
            if (lane == 0) out[n*T + t] = acc;
            return;
        }

        // ---- K = exp2(Earg + c3*A) (row-shifted kernel) ----
        float K[MN];
        {
            float4 e0 = *(const float4*)&eargs[t][ei][0];
            float4 e1 = *(const float4*)&eargs[t][ei][4];
            float2 e2 = *(const float2*)&eargs[t][ei][8];
            float ee[MN] = {e0.x,e0.y,e0.z,e0.w,e1.x,e1.y,e1.z,e1.w,e2.x,e2.y};
            #pragma unroll
            for (int l = 0; l < MN; l++) K[l] = ex2(fmaf(c3, A[l], ee[l]));
        }

        // ---- stage fresh K into grows (all its G readers are done) --------
        __syncwarp();
        if (rowact) {
            *(float4*)&grows[t][lane][0] = make_float4(K[0],K[1],K[2],K[3]);
            *(float4*)&grows[t][lane][4] = make_float4(K[4],K[5],K[6],K[7]);
            *(float2*)&grows[t][lane][8] = make_float2(K[8],K[9]);
        }
        __syncwarp();
        float KT[S];
        #pragma unroll
        for (int ii = 0; ii < S; ii++) KT[ii] = grows[t][ii][lcol];

        // ---- Sinkhorn (scaling domain): v/w via broadcast smem ------------
        float w;
        {   // iter 1 peeled: v == 1
            float rs = K[0]+K[1]+K[2]+K[3]+K[4]+K[5]+K[6]+K[7]+K[8]+K[9];
            w = rowact ? __fdividef(1.0f / S, rs) : 0.f;
            if (rowact) wbuf[t][lane] = w;
            __syncwarp();
            if (colact) {
                float4 w0 = *(const float4*)&wbuf[t][0];
                float4 w1 = *(const float4*)&wbuf[t][4];
                float4 w2 = *(const float4*)&wbuf[t][8];
                float4 w3 = *(const float4*)&wbuf[t][12];
                float  w4 = wbuf[t][16];
                float cs = KT[0]*w0.x + KT[1]*w0.y + KT[2]*w0.z + KT[3]*w0.w
                         + KT[4]*w1.x + KT[5]*w1.y + KT[6]*w1.z + KT[7]*w1.w
                         + KT[8]*w2.x + KT[9]*w2.y + KT[10]*w2.z + KT[11]*w2.w
                         + KT[12]*w3.x + KT[13]*w3.y + KT[14]*w3.z + KT[15]*w3.w
                         + KT[16]*w4;
                vbuf[t][lane] = __fdividef(qcol, cs);
            }
            __syncwarp();
        }
        #pragma unroll
        for (int si = 1; si < N_SINK; si++) {
            float4 b0 = *(const float4*)&vbuf[t][0];
            float4 b1 = *(const float4*)&vbuf[t][4];
            float2 b2 = *(const float2*)&vbuf[t][8];
            float rs = K[0]*b0.x + K[1]*b0.y + K[2]*b0.z + K[3]*b0.w
                     + K[4]*b1.x + K[5]*b1.y + K[6]*b1.z + K[7]*b1.w
                     + K[8]*b2.x + K[9]*b2.y;
            w = rowact ? __fdividef(1.0f / S, rs) : 0.f;
            if (rowact) wbuf[t][lane] = w;
            __syncwarp();
            if (colact) {
                float4 w0 = *(const float4*)&wbuf[t][0];
                float4 w1 = *(const float4*)&wbuf[t][4];
                float4 w2 = *(const float4*)&wbuf[t][8];
                float4 w3 = *(const float4*)&wbuf[t][12];
                float  w4 = wbuf[t][16];
                float cs = KT[0]*w0.x + KT[1]*w0.y + KT[2]*w0.z + KT[3]*w0.w
                         + KT[4]*w1.x + KT[5]*w1.y + KT[6]*w1.z + KT[7]*w1.w
                         + KT[8]*w2.x + KT[9]*w2.y + KT[10]*w2.z + KT[11]*w2.w
                         + KT[12]*w3.x + KT[13]*w3.y + KT[14]*w3.z + KT[15]*w3.w
                         + KT[16]*w4;
                vbuf[t][lane] = __fdividef(qcol, cs);
            }
            __syncwarp();
        }

        // ---- fold: grows = w * K .* v^T  (next outer's G) -----------------
        {
            float4 b0 = *(const float4*)&vbuf[t][0];
            float4 b1 = *(const float4*)&vbuf[t][4];
            float2 b2 = *(const float2*)&vbuf[t][8];
            if (rowact) {
                *(float4*)&grows[t][lane][0] = make_float4(w*K[0]*b0.x, w*K[1]*b0.y, w*K[2]*b0.z, w*K[3]*b0.w);
                *(float4*)&grows[t][lane][4] = make_float4(w*K[4]*b1.x, w*K[5]*b1.y, w*K[6]*b1.z, w*K[7]*b1.w);
                *(float2*)&grows[t][lane][8] = make_float2(w*K[8]*b2.x, w*K[9]*b2.y);
            }
        }
    }
}

// ---------------- launch ----------------------------------------------------
extern "C" void kernel_launch(void* const* d_in, const int* in_sizes, int n_in,
                              void* d_out, int out_size) {
    const float* x      = (const float*)d_in[0];
    const int*   edge   = (const int*)  d_in[1];
    const float* tmpl   = (const float*)d_in[2];
    const float* tf     = (const float*)d_in[3];
    const float* q0     = (const float*)d_in[4];
    const float* alpha0 = (const float*)d_in[5];
    const int*   dst    = edge + N_NODES*DEG;
    float* out = (float*)d_out;

    pm_pre_kernel<<<N_NODES/NPB, 512>>>(x, tf, tmpl, q0, alpha0);
    ltfgw_kernel<<<N_NODES, 320>>>(dst, out);
}